// round 3
// baseline (speedup 1.0000x reference)
#include <cuda_runtime.h>

// RipsLayer: outputs are pure gathers of pairwise distances at given index
// pairs — no need for the N x N distance matrix the reference materializes.
//
// Output layout (flattened tuple order, fp32):
//   [0,              2*F0)        finite_dgm0 row-major: (0, dist) per row
//   [2*F0,           2*F0+E0)     essential_dgm0: zeros
//   [2*F0+E0,        +2*F1)       finite_dgm1 row-major: idx1_finite seen as
//                                 (2*F1) index-pairs -> one dist each
//   [.. ,            +E1)         essential_dgm1: one dist per row
//
// One thread per output element; total = 2*F0 + E0 + 2*F1 + E1 (~24.6K).

__device__ __forceinline__ float pair_dist(const float* __restrict__ X,
                                           int a, int b) {
    // X is [N,3] row-major fp32. Same math as reference: sum of squared
    // diffs then sqrt, all in fp32.
    float ax = __ldg(X + 3 * a + 0);
    float ay = __ldg(X + 3 * a + 1);
    float az = __ldg(X + 3 * a + 2);
    float bx = __ldg(X + 3 * b + 0);
    float by = __ldg(X + 3 * b + 1);
    float bz = __ldg(X + 3 * b + 2);
    float dx = ax - bx;
    float dy = ay - by;
    float dz = az - bz;
    return sqrtf(fmaf(dx, dx, fmaf(dy, dy, dz * dz)));
}

__global__ void rips_layer_kernel(const float* __restrict__ X,
                                  const int* __restrict__ idx0_finite,   // [F0,3]
                                  const int* __restrict__ idx1_finite,   // [F1,4]
                                  const int* __restrict__ idx1_essential,// [E1,2]
                                  float* __restrict__ out,
                                  int F0, int E0, int F1, int E1,
                                  int total) {
    int i = blockIdx.x * blockDim.x + threadIdx.x;
    if (i >= total) return;

    const int o1 = 2 * F0;        // start of essential_dgm0
    const int o2 = o1 + E0;       // start of finite_dgm1 (flattened)
    const int o3 = o2 + 2 * F1;   // start of essential_dgm1

    float val = 0.0f;

    if (i < o1) {
        // finite_dgm0: even cols are birth=0, odd cols are death = edge length
        if (i & 1) {
            int r = i >> 1;
            int a = __ldg(idx0_finite + 3 * r + 1);
            int b = __ldg(idx0_finite + 3 * r + 2);
            val = pair_dist(X, a, b);
        }
    } else if (i < o2) {
        // essential_dgm0: zeros
        val = 0.0f;
    } else if (i < o3) {
        // finite_dgm1: idx1_finite reshaped to (2*F1, 2) index pairs
        int j = i - o2;
        int a = __ldg(idx1_finite + 2 * j + 0);
        int b = __ldg(idx1_finite + 2 * j + 1);
        val = pair_dist(X, a, b);
    } else {
        // essential_dgm1
        int k = i - o3;
        int a = __ldg(idx1_essential + 2 * k + 0);
        int b = __ldg(idx1_essential + 2 * k + 1);
        val = pair_dist(X, a, b);
    }

    out[i] = val;
}

extern "C" void kernel_launch(void* const* d_in, const int* in_sizes, int n_in,
                              void* d_out, int out_size) {
    const float* X              = (const float*)d_in[0];
    const int*   idx0_finite    = (const int*)d_in[1];
    // d_in[2] = idx0_essential — only its COUNT matters (zeros in output)
    const int*   idx1_finite    = (const int*)d_in[3];
    const int*   idx1_essential = (const int*)d_in[4];

    int F0 = in_sizes[1] / 3;   // idx0_finite is [F0,3]
    int E0 = in_sizes[2];       // idx0_essential is [E0]
    int F1 = in_sizes[3] / 4;   // idx1_finite is [F1,4]
    int E1 = in_sizes[4] / 2;   // idx1_essential is [E1,2]

    int total = 2 * F0 + E0 + 2 * F1 + E1;  // == out_size

    const int threads = 256;
    int blocks = (total + threads - 1) / threads;
    rips_layer_kernel<<<blocks, threads>>>(
        X, idx0_finite, idx1_finite, idx1_essential,
        (float*)d_out, F0, E0, F1, E1, total);
}

// round 4
// speedup vs baseline: 1.0435x; 1.0435x over previous
#include <cuda_runtime.h>

// RipsLayer: pure gather of pairwise distances at given index pairs.
//
// Output layout (flattened tuple order, fp32):
//   [0, 2*F0)            finite_dgm0 rows: (0, dist)      -> float2 store
//   [2*F0, +E0)          essential_dgm0: zeros
//   [.., +2*F1)          finite_dgm1 rows: (dist, dist)   -> region starts at
//                        odd float offset (E0=1), so scalar stores
//   [.., +E1)            essential_dgm1: one dist per row
//
// Row-per-thread: F0 + E0 + F1 + E1 threads (~12.3K), 128-thread blocks for
// max SM spread (1 CTA/SM, 4 warps).

__device__ __forceinline__ float pair_dist(const float* __restrict__ X,
                                           int a, int b) {
    float ax = __ldg(X + 3 * a + 0);
    float ay = __ldg(X + 3 * a + 1);
    float az = __ldg(X + 3 * a + 2);
    float bx = __ldg(X + 3 * b + 0);
    float by = __ldg(X + 3 * b + 1);
    float bz = __ldg(X + 3 * b + 2);
    float dx = ax - bx;
    float dy = ay - by;
    float dz = az - bz;
    return sqrtf(fmaf(dx, dx, fmaf(dy, dy, dz * dz)));
}

__global__ void __launch_bounds__(128)
rips_layer_kernel(const float* __restrict__ X,
                  const int* __restrict__ idx0_finite,    // [F0,3]
                  const int* __restrict__ idx1_finite,    // [F1,4] 16B-aligned rows
                  const int* __restrict__ idx1_essential, // [E1,2]
                  float* __restrict__ out,
                  int F0, int E0, int F1, int E1) {
    int i = blockIdx.x * blockDim.x + threadIdx.x;

    const int T1 = F0;            // essential_dgm0 threads start
    const int T2 = T1 + E0;       // finite_dgm1 row threads start
    const int T3 = T2 + F1;       // essential_dgm1 threads start
    const int total = T3 + E1;
    if (i >= total) return;

    const int o1 = 2 * F0;        // out: essential_dgm0 start
    const int o2 = o1 + E0;       // out: finite_dgm1 start (odd offset)
    const int o3 = o2 + 2 * F1;   // out: essential_dgm1 start

    if (i < T1) {
        // finite_dgm0 row i: (birth=0, death=dist(idx[3i+1], idx[3i+2]))
        int a = __ldg(idx0_finite + 3 * i + 1);
        int b = __ldg(idx0_finite + 3 * i + 2);
        float d = pair_dist(X, a, b);
        // out base is 256B-aligned, offset 2*i floats -> 8B aligned
        reinterpret_cast<float2*>(out)[i] = make_float2(0.0f, d);
    } else if (i < T2) {
        // essential_dgm0: zero
        out[o1 + (i - T1)] = 0.0f;
    } else if (i < T3) {
        // finite_dgm1 row j: indices (a0,b0,a1,b1) in one 16B load
        int j = i - T2;
        int4 idx = __ldg(reinterpret_cast<const int4*>(idx1_finite) + j);
        float d0 = pair_dist(X, idx.x, idx.y);
        float d1 = pair_dist(X, idx.z, idx.w);
        // region starts at odd float offset -> scalar stores
        out[o2 + 2 * j + 0] = d0;
        out[o2 + 2 * j + 1] = d1;
    } else {
        // essential_dgm1 row k
        int k = i - T3;
        int a = __ldg(idx1_essential + 2 * k + 0);
        int b = __ldg(idx1_essential + 2 * k + 1);
        out[o3 + k] = pair_dist(X, a, b);
    }
}

extern "C" void kernel_launch(void* const* d_in, const int* in_sizes, int n_in,
                              void* d_out, int out_size) {
    const float* X              = (const float*)d_in[0];
    const int*   idx0_finite    = (const int*)d_in[1];
    // d_in[2] = idx0_essential — only its COUNT matters (zeros in output)
    const int*   idx1_finite    = (const int*)d_in[3];
    const int*   idx1_essential = (const int*)d_in[4];

    int F0 = in_sizes[1] / 3;   // idx0_finite [F0,3]
    int E0 = in_sizes[2];       // idx0_essential [E0]
    int F1 = in_sizes[3] / 4;   // idx1_finite [F1,4]
    int E1 = in_sizes[4] / 2;   // idx1_essential [E1,2]

    int total_threads = F0 + E0 + F1 + E1;

    const int threads = 128;
    int blocks = (total_threads + threads - 1) / threads;
    rips_layer_kernel<<<blocks, threads>>>(
        X, idx0_finite, idx1_finite, idx1_essential,
        (float*)d_out, F0, E0, F1, E1);
}